// round 2
// baseline (speedup 1.0000x reference)
#include <cuda_runtime.h>
#include <math.h>

#define NN   100000
#define EE   3200000
#define FIN  256
#define HID  16
#define CC   40

#define SCAN_T 512
#define SCAN_B ((NN + SCAN_T - 1) / SCAN_T)   // 196

// ---------------- scratch (device globals; no allocation allowed) ------------
__device__ int   g_rowptr[NN + 1];
__device__ int   g_fill[NN];
__device__ int   g_col[EE];
__device__ float g_dinv[NN];
__device__ float g_f1[NN * HID];   // dinv * (x @ W1)
__device__ float g_f2[NN * CC];    // dinv * (relu(h1) @ W2)
__device__ int   g_bsum[256];

// ---------------- CSR build -------------------------------------------------
__global__ void k_zero() {
    int i = blockIdx.x * blockDim.x + threadIdx.x;
    if (i < NN) g_fill[i] = 0;
}

__global__ void k_hist(const int* __restrict__ ei) {
    int e = blockIdx.x * blockDim.x + threadIdx.x;
    if (e < EE) {
        int d = ei[EE + e];               // dst row (int32 edge index)
        atomicAdd(&g_fill[d], 1);
    }
}

__global__ void k_scan_part() {
    __shared__ int s[SCAN_T];
    int i = blockIdx.x * SCAN_T + threadIdx.x;
    int v = (i < NN) ? g_fill[i] : 0;
    s[threadIdx.x] = v;
    for (int off = 1; off < SCAN_T; off <<= 1) {
        __syncthreads();
        int t = (threadIdx.x >= off) ? s[threadIdx.x - off] : 0;
        __syncthreads();
        s[threadIdx.x] += t;
    }
    __syncthreads();
    if (i < NN) {
        g_rowptr[i] = s[threadIdx.x] - v;                 // block-local exclusive
        g_dinv[i]   = rsqrtf((float)(v + 1));             // deg = indeg + self loop
    }
    if (threadIdx.x == SCAN_T - 1) g_bsum[blockIdx.x] = s[threadIdx.x];
}

__global__ void k_scan_top() {
    __shared__ int s[256];
    int t = threadIdx.x;
    int v = (t < SCAN_B) ? g_bsum[t] : 0;
    s[t] = v;
    for (int off = 1; off < 256; off <<= 1) {
        __syncthreads();
        int u = (t >= off) ? s[t - off] : 0;
        __syncthreads();
        s[t] += u;
    }
    __syncthreads();
    if (t < SCAN_B) g_bsum[t] = s[t] - v;                 // exclusive
}

__global__ void k_scan_add() {
    int i = blockIdx.x * SCAN_T + threadIdx.x;
    if (i < NN) {
        int r = g_rowptr[i] + g_bsum[blockIdx.x];
        g_rowptr[i] = r;
        g_fill[i]   = r;                                  // fill cursor
    }
    if (blockIdx.x == 0 && threadIdx.x == 0) g_rowptr[NN] = EE;
}

__global__ void k_scatter(const int* __restrict__ ei) {
    int e = blockIdx.x * blockDim.x + threadIdx.x;
    if (e < EE) {
        int s = ei[e];
        int d = ei[EE + e];
        int p = atomicAdd(&g_fill[d], 1);
        g_col[p] = s;
    }
}

// ---------------- layer 1 dense GEMM: g_f1 = dinv * (x @ W1) ----------------
__global__ void k_gemm1(const float* __restrict__ x, const float* __restrict__ W1) {
    __shared__ float Ws[FIN * HID];                        // 16 KB
    for (int i = threadIdx.x; i < FIN * HID; i += blockDim.x) Ws[i] = W1[i];
    __syncthreads();

    int row = blockIdx.x * blockDim.x + threadIdx.x;
    if (row >= NN) return;

    float4 a0 = {0,0,0,0}, a1 = {0,0,0,0}, a2 = {0,0,0,0}, a3 = {0,0,0,0};
    const float4* xr = (const float4*)(x + (size_t)row * FIN);

    #pragma unroll 8
    for (int kk = 0; kk < FIN / 4; kk++) {
        float4 xv = __ldg(&xr[kk]);
        float xs[4] = {xv.x, xv.y, xv.z, xv.w};
        #pragma unroll
        for (int c = 0; c < 4; c++) {
            const float4* wr = (const float4*)&Ws[(kk * 4 + c) * HID];
            float xc = xs[c];
            float4 w0 = wr[0], w1 = wr[1], w2 = wr[2], w3 = wr[3];
            a0.x += xc * w0.x; a0.y += xc * w0.y; a0.z += xc * w0.z; a0.w += xc * w0.w;
            a1.x += xc * w1.x; a1.y += xc * w1.y; a1.z += xc * w1.z; a1.w += xc * w1.w;
            a2.x += xc * w2.x; a2.y += xc * w2.y; a2.z += xc * w2.z; a2.w += xc * w2.w;
            a3.x += xc * w3.x; a3.y += xc * w3.y; a3.z += xc * w3.z; a3.w += xc * w3.w;
        }
    }
    float dv = g_dinv[row];
    float4* o = (float4*)&g_f1[(size_t)row * HID];
    a0.x *= dv; a0.y *= dv; a0.z *= dv; a0.w *= dv;
    a1.x *= dv; a1.y *= dv; a1.z *= dv; a1.w *= dv;
    a2.x *= dv; a2.y *= dv; a2.z *= dv; a2.w *= dv;
    a3.x *= dv; a3.y *= dv; a3.z *= dv; a3.w *= dv;
    o[0] = a0; o[1] = a1; o[2] = a2; o[3] = a3;
}

// -------- layer-1 aggregation + relu + fused GEMM2: g_f2 = dinv*(h@W2) ------
__global__ void k_agg1(const float* __restrict__ b1, const float* __restrict__ W2) {
    __shared__ float W2s[HID * CC];                        // 640 floats
    __shared__ float b1s[HID];
    for (int i = threadIdx.x; i < HID * CC; i += blockDim.x) W2s[i] = W2[i];
    if (threadIdx.x < HID) b1s[threadIdx.x] = b1[threadIdx.x];
    __syncthreads();

    int lane = threadIdx.x & 31;
    int node = blockIdx.x * (blockDim.x >> 5) + (threadIdx.x >> 5);
    if (node >= NN) return;

    int start = g_rowptr[node];
    int cnt   = g_rowptr[node + 1] - start;

    float acc = 0.f;
    for (int base = 0; base < cnt; base += 32) {
        int t    = base + lane;
        int cidx = (t < cnt) ? g_col[start + t] : 0;
        int m    = min(32, cnt - base);
        for (int j = 0; j < m; j += 2) {
            int i0 = __shfl_sync(0xffffffffu, cidx, j);
            int i1 = (j + 1 < m) ? __shfl_sync(0xffffffffu, cidx, j + 1) : i0;
            int myi = (lane < 16) ? i0 : i1;
            if (lane < 16 || (j + 1 < m))
                acc += g_f1[(size_t)myi * HID + (lane & 15)];
        }
    }
    if (lane < 16) acc += g_f1[(size_t)node * HID + lane];   // self loop (once)
    acc += __shfl_xor_sync(0xffffffffu, acc, 16);            // combine halves

    float dv = g_dinv[node];
    float h  = fmaxf(dv * acc + b1s[lane & 15], 0.f);        // lane holds h[lane&15]

    // fused 16x40 GEMM via shuffles; lane -> col lane, lanes 0-7 also col 32+lane
    float t2a = 0.f, t2b = 0.f;
    #pragma unroll
    for (int k = 0; k < HID; k++) {
        float hk = __shfl_sync(0xffffffffu, h, k);
        t2a += hk * W2s[k * CC + lane];
        if (lane < 8) t2b += hk * W2s[k * CC + 32 + lane];
    }
    g_f2[(size_t)node * CC + lane] = dv * t2a;
    if (lane < 8) g_f2[(size_t)node * CC + 32 + lane] = dv * t2b;
}

// -------- layer-2 aggregation + bias + log_softmax --------------------------
__global__ void k_agg2(const float* __restrict__ b2, float* __restrict__ out) {
    __shared__ float b2s[CC];
    if (threadIdx.x < CC) b2s[threadIdx.x] = b2[threadIdx.x];
    __syncthreads();

    int lane = threadIdx.x & 31;
    int node = blockIdx.x * (blockDim.x >> 5) + (threadIdx.x >> 5);
    if (node >= NN) return;

    int start = g_rowptr[node];
    int cnt   = g_rowptr[node + 1] - start;

    float acc0 = 0.f, acc1 = 0.f;
    for (int base = 0; base < cnt; base += 32) {
        int t    = base + lane;
        int cidx = (t < cnt) ? g_col[start + t] : 0;
        int m    = min(32, cnt - base);
        for (int j = 0; j < m; j++) {
            int idx = __shfl_sync(0xffffffffu, cidx, j);
            acc0 += g_f2[(size_t)idx * CC + lane];
            if (lane < 8) acc1 += g_f2[(size_t)idx * CC + 32 + lane];
        }
    }
    acc0 += g_f2[(size_t)node * CC + lane];                  // self loop
    if (lane < 8) acc1 += g_f2[(size_t)node * CC + 32 + lane];

    float dv = g_dinv[node];
    float v0 = dv * acc0 + b2s[lane];
    float v1 = (lane < 8) ? (dv * acc1 + b2s[32 + lane]) : -3.4e38f;

    float M = fmaxf(v0, v1);
    #pragma unroll
    for (int off = 16; off > 0; off >>= 1)
        M = fmaxf(M, __shfl_xor_sync(0xffffffffu, M, off));

    float se = expf(v0 - M) + ((lane < 8) ? expf(v1 - M) : 0.f);
    #pragma unroll
    for (int off = 16; off > 0; off >>= 1)
        se += __shfl_xor_sync(0xffffffffu, se, off);

    float L = logf(se);
    out[(size_t)node * CC + lane] = v0 - M - L;
    if (lane < 8) out[(size_t)node * CC + 32 + lane] = v1 - M - L;
}

// ---------------- launch ----------------------------------------------------
extern "C" void kernel_launch(void* const* d_in, const int* in_sizes, int n_in,
                              void* d_out, int out_size) {
    const float* x  = (const float*)d_in[0];
    const int*   ei = (const int*)d_in[1];     // int32 edge index (JAX x64 disabled)
    const float* W1 = (const float*)d_in[2];
    const float* b1 = (const float*)d_in[3];
    const float* W2 = (const float*)d_in[4];
    const float* b2 = (const float*)d_in[5];
    float*       out = (float*)d_out;

    const int EB = (EE + 255) / 256;        // 12500
    const int NB = (NN + 255) / 256;        // 391

    k_zero<<<NB, 256>>>();
    k_hist<<<EB, 256>>>(ei);
    k_scan_part<<<SCAN_B, SCAN_T>>>();
    k_scan_top<<<1, 256>>>();
    k_scan_add<<<SCAN_B, SCAN_T>>>();
    k_scatter<<<EB, 256>>>(ei);
    k_gemm1<<<NB, 256>>>(x, W1);
    // warp per node, 8 warps per block
    k_agg1<<<(NN + 7) / 8, 256>>>(b1, W2);
    k_agg2<<<(NN + 7) / 8, 256>>>(b2, out);
}

// round 3
// speedup vs baseline: 1.3146x; 1.3146x over previous
#include <cuda_runtime.h>
#include <math.h>

#define NN   100000
#define EE   3200000
#define FIN  256
#define HID  16
#define CC   40
#define FULLM 0xffffffffu

#define SCAN_T 512
#define SCAN_B ((NN + SCAN_T - 1) / SCAN_T)   // 196

// ---------------- scratch (device globals; no allocation allowed) ------------
__device__ int    g_rowptr[NN + 1];
__device__ int    g_fill[NN];
__device__ int    g_col[EE];
__device__ float  g_dinv[NN];
__device__ float4 g_f1[NN * 4];   // dinv * (x @ W1), 16 floats/node
__device__ float4 g_f2[NN * 4];   // dinv * relu(h1), 16 floats/node
__device__ int    g_bsum[256];

#define FFMA2(d, a, b) asm("fma.rn.f32x2 %0, %1, %2, %0;" : "+l"(d) : "l"(a), "l"(b))

// ---------------- CSR build -------------------------------------------------
__global__ void k_zero() {
    int i = blockIdx.x * blockDim.x + threadIdx.x;
    if (i < NN) g_fill[i] = 0;
}

__global__ void k_hist(const int* __restrict__ ei) {
    int i = blockIdx.x * blockDim.x + threadIdx.x;
    if (i < EE / 4) {
        int4 d = ((const int4*)(ei + EE))[i];
        atomicAdd(&g_fill[d.x], 1);
        atomicAdd(&g_fill[d.y], 1);
        atomicAdd(&g_fill[d.z], 1);
        atomicAdd(&g_fill[d.w], 1);
    }
}

__global__ void k_scan_part() {
    __shared__ int s[SCAN_T];
    int i = blockIdx.x * SCAN_T + threadIdx.x;
    int v = (i < NN) ? g_fill[i] : 0;
    s[threadIdx.x] = v;
    for (int off = 1; off < SCAN_T; off <<= 1) {
        __syncthreads();
        int t = (threadIdx.x >= off) ? s[threadIdx.x - off] : 0;
        __syncthreads();
        s[threadIdx.x] += t;
    }
    __syncthreads();
    if (i < NN) {
        g_rowptr[i] = s[threadIdx.x] - v;                 // block-local exclusive
        g_dinv[i]   = rsqrtf((float)(v + 1));             // deg = indeg + self loop
    }
    if (threadIdx.x == SCAN_T - 1) g_bsum[blockIdx.x] = s[threadIdx.x];
}

__global__ void k_scan_top() {
    __shared__ int s[256];
    int t = threadIdx.x;
    int v = (t < SCAN_B) ? g_bsum[t] : 0;
    s[t] = v;
    for (int off = 1; off < 256; off <<= 1) {
        __syncthreads();
        int u = (t >= off) ? s[t - off] : 0;
        __syncthreads();
        s[t] += u;
    }
    __syncthreads();
    if (t < SCAN_B) g_bsum[t] = s[t] - v;                 // exclusive
}

__global__ void k_scan_add() {
    int i = blockIdx.x * SCAN_T + threadIdx.x;
    if (i < NN) {
        int r = g_rowptr[i] + g_bsum[blockIdx.x];
        g_rowptr[i] = r;
        g_fill[i]   = r;                                  // fill cursor
    }
    if (blockIdx.x == 0 && threadIdx.x == 0) g_rowptr[NN] = EE;
}

__global__ void k_scatter(const int* __restrict__ ei) {
    int i = blockIdx.x * blockDim.x + threadIdx.x;
    if (i < EE / 4) {
        int4 s = ((const int4*)ei)[i];
        int4 d = ((const int4*)(ei + EE))[i];
        int p;
        p = atomicAdd(&g_fill[d.x], 1); g_col[p] = s.x;
        p = atomicAdd(&g_fill[d.y], 1); g_col[p] = s.y;
        p = atomicAdd(&g_fill[d.z], 1); g_col[p] = s.z;
        p = atomicAdd(&g_fill[d.w], 1); g_col[p] = s.w;
    }
}

// ---------------- layer-1 dense GEMM: g_f1 = dinv * (x @ W1) ----------------
// f32x2 packed FMA: accumulators hold column pairs (2j, 2j+1).
__global__ void k_gemm1(const float* __restrict__ x, const float* __restrict__ W1) {
    __shared__ __align__(16) float Ws[FIN * HID];          // 16 KB
    for (int i = threadIdx.x; i < FIN * HID; i += blockDim.x) Ws[i] = W1[i];
    __syncthreads();

    int row = blockIdx.x * blockDim.x + threadIdx.x;
    if (row >= NN) return;

    unsigned long long acc[8];
    #pragma unroll
    for (int j = 0; j < 8; j++) acc[j] = 0ull;            // bits 0 == (0.f, 0.f)

    const float4* xr = (const float4*)(x + (size_t)row * FIN);

    #pragma unroll 4
    for (int kk = 0; kk < FIN / 4; kk++) {
        float4 xv = __ldg(&xr[kk]);
        float xs[4] = {xv.x, xv.y, xv.z, xv.w};
        #pragma unroll
        for (int c = 0; c < 4; c++) {
            unsigned long long xp;
            asm("mov.b64 %0, {%1, %1};" : "=l"(xp) : "f"(xs[c]));
            const ulonglong2* wr = (const ulonglong2*)&Ws[(kk * 4 + c) * HID];
            ulonglong2 w01 = wr[0], w23 = wr[1], w45 = wr[2], w67 = wr[3];
            FFMA2(acc[0], xp, w01.x);
            FFMA2(acc[1], xp, w01.y);
            FFMA2(acc[2], xp, w23.x);
            FFMA2(acc[3], xp, w23.y);
            FFMA2(acc[4], xp, w45.x);
            FFMA2(acc[5], xp, w45.y);
            FFMA2(acc[6], xp, w67.x);
            FFMA2(acc[7], xp, w67.y);
        }
    }

    float r[16];
    #pragma unroll
    for (int j = 0; j < 8; j++)
        asm("mov.b64 {%0, %1}, %2;" : "=f"(r[2*j]), "=f"(r[2*j+1]) : "l"(acc[j]));

    float dv = g_dinv[row];
    float4* o = &g_f1[(size_t)row * 4];
    o[0] = make_float4(r[0]*dv,  r[1]*dv,  r[2]*dv,  r[3]*dv);
    o[1] = make_float4(r[4]*dv,  r[5]*dv,  r[6]*dv,  r[7]*dv);
    o[2] = make_float4(r[8]*dv,  r[9]*dv,  r[10]*dv, r[11]*dv);
    o[3] = make_float4(r[12]*dv, r[13]*dv, r[14]*dv, r[15]*dv);
}

// -------- shared 16-dim CSR gather: quad-per-edge, float4 loads -------------
// On return every lane holds the aggregate (incl. self loop) for features
// (lane&3)*4 .. +3 as a float4.
__device__ __forceinline__ float4 warp_gather16(const float4* __restrict__ feat,
                                                int node, int lane) {
    int start = g_rowptr[node];
    int cnt   = g_rowptr[node + 1] - start;
    int q     = lane >> 2;          // quad id: 8 edges in flight per step
    int fs    = lane & 3;           // float4 slice within the 16-float row

    float4 acc = make_float4(0.f, 0.f, 0.f, 0.f);
    for (int base = 0; base < cnt; base += 32) {
        int t    = base + lane;
        int cidx = (t < cnt) ? g_col[start + t] : 0;
        int m    = min(32, cnt - base);
        for (int j = 0; j < m; j += 8) {
            int src = __shfl_sync(FULLM, cidx, j + q);
            if (j + q < m) {
                float4 v = feat[(size_t)src * 4 + fs];
                acc.x += v.x; acc.y += v.y; acc.z += v.z; acc.w += v.w;
            }
        }
    }
    // reduce the 8 quads
    #pragma unroll
    for (int off = 4; off <= 16; off <<= 1) {
        acc.x += __shfl_xor_sync(FULLM, acc.x, off);
        acc.y += __shfl_xor_sync(FULLM, acc.y, off);
        acc.z += __shfl_xor_sync(FULLM, acc.z, off);
        acc.w += __shfl_xor_sync(FULLM, acc.w, off);
    }
    // self loop (each lane's copy gets it exactly once)
    float4 sv = feat[(size_t)node * 4 + fs];
    acc.x += sv.x; acc.y += sv.y; acc.z += sv.z; acc.w += sv.w;
    return acc;
}

// -------- layer-1 aggregation + relu: g_f2 = dinv * relu(dinv*agg + b1) -----
__global__ void k_agg1(const float* __restrict__ b1) {
    __shared__ __align__(16) float b1s[HID];
    if (threadIdx.x < HID) b1s[threadIdx.x] = b1[threadIdx.x];
    __syncthreads();

    int lane = threadIdx.x & 31;
    int node = blockIdx.x * (blockDim.x >> 5) + (threadIdx.x >> 5);
    if (node >= NN) return;

    float4 acc = warp_gather16(g_f1, node, lane);

    float dv = g_dinv[node];
    float4 bv = ((const float4*)b1s)[lane & 3];
    float4 h;
    h.x = fmaxf(dv * acc.x + bv.x, 0.f) * dv;
    h.y = fmaxf(dv * acc.y + bv.y, 0.f) * dv;
    h.z = fmaxf(dv * acc.z + bv.z, 0.f) * dv;
    h.w = fmaxf(dv * acc.w + bv.w, 0.f) * dv;

    if (lane < 4) g_f2[(size_t)node * 4 + lane] = h;       // quad 0 stores the row
}

// -------- layer-2 aggregation + fused 16x40 GEMM + log_softmax --------------
__global__ void k_agg2(const float* __restrict__ W2, const float* __restrict__ b2,
                       float* __restrict__ out) {
    __shared__ float W2s[HID * 64];                        // padded cols (junk beyond 40 unused)
    __shared__ float b2s[CC];
    for (int i = threadIdx.x; i < HID * 64; i += blockDim.x) W2s[i] = 0.f;
    __syncthreads();
    for (int i = threadIdx.x; i < HID * CC; i += blockDim.x) {
        int k = i / CC, c = i % CC;
        W2s[k * 64 + c] = W2[i];
    }
    if (threadIdx.x < CC) b2s[threadIdx.x] = b2[threadIdx.x];
    __syncthreads();

    int lane = threadIdx.x & 31;
    int node = blockIdx.x * (blockDim.x >> 5) + (threadIdx.x >> 5);
    if (node >= NN) return;

    float4 acc = warp_gather16(g_f2, node, lane);

    // every lane has features (lane&3)*4..+3; broadcast all 16 and do the GEMM
    float v0 = 0.f, v1 = 0.f;
    #pragma unroll
    for (int k = 0; k < HID; k++) {
        float comp = ((k & 3) == 0) ? acc.x : ((k & 3) == 1) ? acc.y
                   : ((k & 3) == 2) ? acc.z : acc.w;
        float tk = __shfl_sync(FULLM, comp, k >> 2);
        v0 += tk * W2s[k * 64 + lane];
        v1 += tk * W2s[k * 64 + 32 + lane];                // only lanes<8 meaningful
    }

    float dv = g_dinv[node];
    float l0 = dv * v0 + b2s[lane];
    float l1 = (lane < 8) ? (dv * v1 + b2s[32 + lane]) : -3.4e38f;

    float M = fmaxf(l0, l1);
    #pragma unroll
    for (int off = 16; off > 0; off >>= 1)
        M = fmaxf(M, __shfl_xor_sync(FULLM, M, off));

    float se = expf(l0 - M) + ((lane < 8) ? expf(l1 - M) : 0.f);
    #pragma unroll
    for (int off = 16; off > 0; off >>= 1)
        se += __shfl_xor_sync(FULLM, se, off);

    float L = logf(se);
    out[(size_t)node * CC + lane] = l0 - M - L;
    if (lane < 8) out[(size_t)node * CC + 32 + lane] = l1 - M - L;
}

// ---------------- launch ----------------------------------------------------
extern "C" void kernel_launch(void* const* d_in, const int* in_sizes, int n_in,
                              void* d_out, int out_size) {
    const float* x  = (const float*)d_in[0];
    const int*   ei = (const int*)d_in[1];     // int32 edge index (JAX x64 disabled)
    const float* W1 = (const float*)d_in[2];
    const float* b1 = (const float*)d_in[3];
    const float* W2 = (const float*)d_in[4];
    const float* b2 = (const float*)d_in[5];
    float*       out = (float*)d_out;

    const int E4B = (EE / 4 + 255) / 256;   // 3125
    const int NB  = (NN + 255) / 256;       // 391

    k_zero<<<NB, 256>>>();
    k_hist<<<E4B, 256>>>(ei);
    k_scan_part<<<SCAN_B, SCAN_T>>>();
    k_scan_top<<<1, 256>>>();
    k_scan_add<<<SCAN_B, SCAN_T>>>();
    k_scatter<<<E4B, 256>>>(ei);
    k_gemm1<<<NB, 256>>>(x, W1);
    // warp per node, 8 warps per block
    k_agg1<<<(NN + 7) / 8, 256>>>(b1);
    k_agg2<<<(NN + 7) / 8, 256>>>(W2, b2, out);
}

// round 7
// speedup vs baseline: 1.4358x; 1.0922x over previous
#include <cuda_runtime.h>
#include <math.h>

#define NN   100000
#define EE   3200000
#define FIN  256
#define HID  16
#define CC   40
#define FULLM 0xffffffffu

#define SCAN_T 512
#define SCAN_B ((NN + SCAN_T - 1) / SCAN_T)   // 196

// ---------------- scratch (device globals; no allocation allowed) ------------
__device__ int      g_rowptr[NN + 1];
__device__ int      g_fill[NN];
__device__ int      g_rank[EE];
__device__ int      g_col[EE];
__device__ float    g_dinv[NN];
__device__ float4   g_f1[NN * 4];   // dinv * (x @ W1), 16 floats/node
__device__ float4   g_f2[NN * 4];   // dinv * relu(h1), 16 floats/node
__device__ unsigned g_flags[SCAN_B];  // decoupled-lookback state: (val<<2)|st

#define FFMA2(d, a, b) asm("fma.rn.f32x2 %0, %1, %2, %0;" : "+l"(d) : "l"(a), "l"(b))

// ---------------- CSR build -------------------------------------------------
__global__ void k_zero() {
    int i = blockIdx.x * blockDim.x + threadIdx.x;
    if (i < NN) g_fill[i] = 0;
    if (i < SCAN_B) g_flags[i] = 0u;
}

// histogram + per-edge within-bucket rank (atomic return value)
__global__ void k_hist(const int* __restrict__ ei) {
    int i = blockIdx.x * blockDim.x + threadIdx.x;
    if (i < EE / 4) {
        int4 d = ((const int4*)(ei + EE))[i];
        int4 r;
        r.x = atomicAdd(&g_fill[d.x], 1);
        r.y = atomicAdd(&g_fill[d.y], 1);
        r.z = atomicAdd(&g_fill[d.z], 1);
        r.w = atomicAdd(&g_fill[d.w], 1);
        ((int4*)g_rank)[i] = r;
    }
}

// single-pass exclusive scan of g_fill -> g_rowptr, plus dinv. Decoupled lookback.
__global__ void k_scan() {
    __shared__ int wt[SCAN_T / 32];
    __shared__ int s_prefix;
    int tid = threadIdx.x, lane = tid & 31, wid = tid >> 5, b = blockIdx.x;
    int i = b * SCAN_T + tid;
    int v = (i < NN) ? g_fill[i] : 0;

    // warp inclusive scan
    int x = v;
    #pragma unroll
    for (int off = 1; off < 32; off <<= 1) {
        int t = __shfl_up_sync(FULLM, x, off);
        if (lane >= off) x += t;
    }
    if (lane == 31) wt[wid] = x;
    __syncthreads();
    if (wid == 0) {
        int w = (lane < SCAN_T / 32) ? wt[lane] : 0;
        #pragma unroll
        for (int off = 1; off < SCAN_T / 32; off <<= 1) {
            int t = __shfl_up_sync(FULLM, w, off);
            if (lane >= off) w += t;
        }
        if (lane < SCAN_T / 32) wt[lane] = w;         // inclusive warp totals
    }
    __syncthreads();
    int block_tot = wt[SCAN_T / 32 - 1];
    int incl = ((wid == 0) ? 0 : wt[wid - 1]) + x;    // inclusive within block

    if (tid == 0) {
        unsigned pub = (b == 0) ? (((unsigned)block_tot << 2) | 2u)
                                : (((unsigned)block_tot << 2) | 1u);
        atomicExch(&g_flags[b], pub);
    }

    if (b == 0) {
        if (tid == 0) s_prefix = 0;
    } else if (wid == 0) {
        int prefix = 0;
        int base = b - 1;
        while (true) {
            int idx = base - lane;
            unsigned w = (idx >= 0) ? *((volatile unsigned*)&g_flags[idx]) : 2u;
            unsigned st = w & 3u;
            unsigned pm = __ballot_sync(FULLM, st == 2u);
            unsigned zm = __ballot_sync(FULLM, st == 0u);
            if (pm) {
                int fp = __ffs(pm) - 1;               // nearest published prefix
                if ((zm & ((1u << fp) - 1u)) == 0) {
                    int c = (lane <= fp) ? (int)(w >> 2) : 0;
                    #pragma unroll
                    for (int off = 16; off; off >>= 1)
                        c += __shfl_xor_sync(FULLM, c, off);
                    prefix += c;
                    break;
                }
            } else if (zm == 0) {                     // window all aggregates
                int c = (int)(w >> 2);
                #pragma unroll
                for (int off = 16; off; off >>= 1)
                    c += __shfl_xor_sync(FULLM, c, off);
                prefix += c;
                base -= 32;
            }
        }
        if (lane == 0) {
            s_prefix = prefix;
            atomicExch(&g_flags[b], (((unsigned)(prefix + block_tot)) << 2) | 2u);
        }
    }
    __syncthreads();

    if (i < NN) {
        g_rowptr[i] = s_prefix + incl - v;            // exclusive prefix
        g_dinv[i]   = rsqrtf((float)(v + 1));         // deg = indeg + self loop
    }
    if (b == SCAN_B - 1 && tid == SCAN_T - 1) g_rowptr[NN] = EE;
}

// scatter with precomputed ranks: no atomics
__global__ void k_scatter(const int* __restrict__ ei) {
    int i = blockIdx.x * blockDim.x + threadIdx.x;
    if (i < EE / 4) {
        int4 s = ((const int4*)ei)[i];
        int4 d = ((const int4*)(ei + EE))[i];
        int4 r = ((const int4*)g_rank)[i];
        g_col[g_rowptr[d.x] + r.x] = s.x;
        g_col[g_rowptr[d.y] + r.y] = s.y;
        g_col[g_rowptr[d.z] + r.z] = s.z;
        g_col[g_rowptr[d.w] + r.w] = s.w;
    }
}

// ---------------- layer-1 dense GEMM: g_f1 = dinv * (x @ W1) ----------------
__global__ void k_gemm1(const float* __restrict__ x, const float* __restrict__ W1) {
    __shared__ __align__(16) float Ws[FIN * HID];          // 16 KB
    for (int i = threadIdx.x; i < FIN * HID; i += blockDim.x) Ws[i] = W1[i];
    __syncthreads();

    int row = blockIdx.x * blockDim.x + threadIdx.x;
    if (row >= NN) return;

    unsigned long long acc[8];
    #pragma unroll
    for (int j = 0; j < 8; j++) acc[j] = 0ull;

    const float4* xr = (const float4*)(x + (size_t)row * FIN);

    #pragma unroll 4
    for (int kk = 0; kk < FIN / 4; kk++) {
        float4 xv = __ldg(&xr[kk]);
        float xs[4] = {xv.x, xv.y, xv.z, xv.w};
        #pragma unroll
        for (int c = 0; c < 4; c++) {
            unsigned long long xp;
            asm("mov.b64 %0, {%1, %1};" : "=l"(xp) : "f"(xs[c]));
            const ulonglong2* wr = (const ulonglong2*)&Ws[(kk * 4 + c) * HID];
            ulonglong2 w01 = wr[0], w23 = wr[1], w45 = wr[2], w67 = wr[3];
            FFMA2(acc[0], xp, w01.x);
            FFMA2(acc[1], xp, w01.y);
            FFMA2(acc[2], xp, w23.x);
            FFMA2(acc[3], xp, w23.y);
            FFMA2(acc[4], xp, w45.x);
            FFMA2(acc[5], xp, w45.y);
            FFMA2(acc[6], xp, w67.x);
            FFMA2(acc[7], xp, w67.y);
        }
    }

    float r[16];
    #pragma unroll
    for (int j = 0; j < 8; j++)
        asm("mov.b64 {%0, %1}, %2;" : "=f"(r[2*j]), "=f"(r[2*j+1]) : "l"(acc[j]));

    float dv = g_dinv[row];
    float4* o = &g_f1[(size_t)row * 4];
    o[0] = make_float4(r[0]*dv,  r[1]*dv,  r[2]*dv,  r[3]*dv);
    o[1] = make_float4(r[4]*dv,  r[5]*dv,  r[6]*dv,  r[7]*dv);
    o[2] = make_float4(r[8]*dv,  r[9]*dv,  r[10]*dv, r[11]*dv);
    o[3] = make_float4(r[12]*dv, r[13]*dv, r[14]*dv, r[15]*dv);
}

// -------- shared 16-dim CSR gather: quad-per-edge, float4 loads -------------
__device__ __forceinline__ float4 warp_gather16(const float4* __restrict__ feat,
                                                int node, int lane) {
    int start = g_rowptr[node];
    int cnt   = g_rowptr[node + 1] - start;
    int q     = lane >> 2;          // quad id: 8 edges in flight per step
    int fs    = lane & 3;           // float4 slice within the 16-float row

    float4 acc = make_float4(0.f, 0.f, 0.f, 0.f);
    for (int base = 0; base < cnt; base += 32) {
        int t    = base + lane;
        int cidx = (t < cnt) ? g_col[start + t] : 0;
        int m    = min(32, cnt - base);
        for (int j = 0; j < m; j += 8) {
            int src = __shfl_sync(FULLM, cidx, j + q);
            if (j + q < m) {
                float4 v = feat[(size_t)src * 4 + fs];
                acc.x += v.x; acc.y += v.y; acc.z += v.z; acc.w += v.w;
            }
        }
    }
    #pragma unroll
    for (int off = 4; off <= 16; off <<= 1) {
        acc.x += __shfl_xor_sync(FULLM, acc.x, off);
        acc.y += __shfl_xor_sync(FULLM, acc.y, off);
        acc.z += __shfl_xor_sync(FULLM, acc.z, off);
        acc.w += __shfl_xor_sync(FULLM, acc.w, off);
    }
    float4 sv = feat[(size_t)node * 4 + fs];              // self loop
    acc.x += sv.x; acc.y += sv.y; acc.z += sv.z; acc.w += sv.w;
    return acc;
}

// -------- layer-1 aggregation + relu: g_f2 = dinv * relu(dinv*agg + b1) -----
__global__ void k_agg1(const float* __restrict__ b1) {
    __shared__ __align__(16) float b1s[HID];
    if (threadIdx.x < HID) b1s[threadIdx.x] = b1[threadIdx.x];
    __syncthreads();

    int lane = threadIdx.x & 31;
    int node = blockIdx.x * (blockDim.x >> 5) + (threadIdx.x >> 5);
    if (node >= NN) return;

    float4 acc = warp_gather16(g_f1, node, lane);

    float dv = g_dinv[node];
    float4 bv = ((const float4*)b1s)[lane & 3];
    float4 h;
    h.x = fmaxf(dv * acc.x + bv.x, 0.f) * dv;
    h.y = fmaxf(dv * acc.y + bv.y, 0.f) * dv;
    h.z = fmaxf(dv * acc.z + bv.z, 0.f) * dv;
    h.w = fmaxf(dv * acc.w + bv.w, 0.f) * dv;

    if (lane < 4) g_f2[(size_t)node * 4 + lane] = h;
}

// -------- layer-2 aggregation + fused 16x40 GEMM + log_softmax --------------
__global__ void k_agg2(const float* __restrict__ W2, const float* __restrict__ b2,
                       float* __restrict__ out) {
    __shared__ float W2s[HID * 64];
    __shared__ float b2s[CC];
    for (int i = threadIdx.x; i < HID * 64; i += blockDim.x) W2s[i] = 0.f;
    __syncthreads();
    for (int i = threadIdx.x; i < HID * CC; i += blockDim.x) {
        int k = i / CC, c = i % CC;
        W2s[k * 64 + c] = W2[i];
    }
    if (threadIdx.x < CC) b2s[threadIdx.x] = b2[threadIdx.x];
    __syncthreads();

    int lane = threadIdx.x & 31;
    int node = blockIdx.x * (blockDim.x >> 5) + (threadIdx.x >> 5);
    if (node >= NN) return;

    float4 acc = warp_gather16(g_f2, node, lane);

    float v0 = 0.f, v1 = 0.f;
    #pragma unroll
    for (int k = 0; k < HID; k++) {
        float comp = ((k & 3) == 0) ? acc.x : ((k & 3) == 1) ? acc.y
                   : ((k & 3) == 2) ? acc.z : acc.w;
        float tk = __shfl_sync(FULLM, comp, k >> 2);
        v0 += tk * W2s[k * 64 + lane];
        v1 += tk * W2s[k * 64 + 32 + lane];
    }

    float dv = g_dinv[node];
    float l0 = dv * v0 + b2s[lane];
    float l1 = (lane < 8) ? (dv * v1 + b2s[32 + lane]) : -3.4e38f;

    float M = fmaxf(l0, l1);
    #pragma unroll
    for (int off = 16; off > 0; off >>= 1)
        M = fmaxf(M, __shfl_xor_sync(FULLM, M, off));

    float se = expf(l0 - M) + ((lane < 8) ? expf(l1 - M) : 0.f);
    #pragma unroll
    for (int off = 16; off > 0; off >>= 1)
        se += __shfl_xor_sync(FULLM, se, off);

    float L = logf(se);
    out[(size_t)node * CC + lane] = l0 - M - L;
    if (lane < 8) out[(size_t)node * CC + 32 + lane] = l1 - M - L;
}

// ---------------- launch ----------------------------------------------------
extern "C" void kernel_launch(void* const* d_in, const int* in_sizes, int n_in,
                              void* d_out, int out_size) {
    const float* x  = (const float*)d_in[0];
    const int*   ei = (const int*)d_in[1];     // int32 edge index
    const float* W1 = (const float*)d_in[2];
    const float* b1 = (const float*)d_in[3];
    const float* W2 = (const float*)d_in[4];
    const float* b2 = (const float*)d_in[5];
    float*       out = (float*)d_out;

    // side stream + events created on first (non-capturing, correctness) call
    static cudaStream_t s1 = nullptr;
    static cudaEvent_t  ev_fork = nullptr, ev_join = nullptr;
    if (!s1) {
        cudaStreamCreateWithFlags(&s1, cudaStreamNonBlocking);
        cudaEventCreateWithFlags(&ev_fork, cudaEventDisableTiming);
        cudaEventCreateWithFlags(&ev_join, cudaEventDisableTiming);
    }

    const int E4B = (EE / 4 + 255) / 256;   // 3125
    const int NB  = (NN + 255) / 256;       // 391

    k_zero<<<NB, 256>>>();
    k_hist<<<E4B, 256>>>(ei);
    k_scan<<<SCAN_B, SCAN_T>>>();           // rowptr + dinv ready here

    // fork: gemm1 (needs only dinv) overlaps scatter
    cudaEventRecord(ev_fork, 0);
    cudaStreamWaitEvent(s1, ev_fork, 0);
    k_gemm1<<<NB, 256, 0, s1>>>(x, W1);
    cudaEventRecord(ev_join, s1);

    k_scatter<<<E4B, 256>>>(ei);

    // join: agg1 needs both scatter (stream 0) and gemm1 (s1)
    cudaStreamWaitEvent(0, ev_join, 0);
    k_agg1<<<(NN + 7) / 8, 256>>>(b1);
    k_agg2<<<(NN + 7) / 8, 256>>>(W2, b2, out);
}